// round 15
// baseline (speedup 1.0000x reference)
#include <cuda_runtime.h>
#include <cuda_bf16.h>
#include <math.h>

// ---- static problem config (matches reference) ----
#define N_ATOMS 16384
#define NUM_BATCH 32
#define ATOMS_PER_BATCH 512
#define N_PAIRS 1048576

#define ALPHA_F       0.401f            // 4/10 + 0.001
#define K2FAC_F       1.5547167f        // 0.25 / ALPHA^2
#define TWO_PI_F      6.283185307179586f
#define SELF_F        0.2262400229976503f   // ALPHA / sqrt(pi)
#define EPS_F         1e-8f
#define FULL 0xFFFFFFFFu

#define REAL_BLOCKS 512                 // 512 blocks * 8 warps * 256 pairs = 1M
#define PAIRS_PER_WARP 256
#define KMAXI 8

// ------------------------------------------------------------------
// Compile-time k-table organized as GROUPS of 4 consecutive mz within
// one (mx,my) column of the canonical half lattice. A warp computes one
// sincos for the first entry of a group and derives the other three by
// complex rotation with the per-atom phasor e^{i*theta_z}.
// canonical: mx>0 | (mx=0 & my>0) | (mx=0 & my=0 & mz>0); 0<|k|^2<=64.
// ------------------------------------------------------------------
struct KGroup { float mx, my, mz0, pad, w0, w1, w2, w3; };

constexpr int ifsqrt(int v) { int r = 0; while ((r + 1) * (r + 1) <= v) r++; return r; }

constexpr int count_groups() {
    int n = 0;
    n += 2;                                        // (0,0): mz 1..8 -> 2 groups
    for (int my = 1; my <= KMAXI; my++) {          // mx=0 columns
        int L = ifsqrt(KMAXI * KMAXI - my * my);
        n += (2 * L + 1 + 3) / 4;
    }
    for (int mx = 1; mx <= KMAXI; mx++) {
        int L2 = ifsqrt(KMAXI * KMAXI - mx * mx);
        for (int my = -L2; my <= L2; my++) {
            int L = ifsqrt(KMAXI * KMAXI - mx * mx - my * my);
            n += (2 * L + 1 + 3) / 4;
        }
    }
    return n;
}
constexpr int NG     = count_groups();
constexpr int NG_PAD = ((NG + 159) / 160) * 160;   // multiple of 160 -> KBg mult of 20
constexpr int KBg    = NG_PAD / 8;                 // chunks of 8 groups
constexpr int JG     = 20;                         // chunk groups per batch
static_assert(KBg % JG == 0, "balanced chunks");
constexpr int CHUNKS_PER_BLOCK = KBg / JG;         // 2

struct KGTable { KGroup g[NG_PAD]; };

constexpr KGTable make_kg() {
    KGTable t{};
    int n = 0;
    // (0,0): mz 1..8
    for (int mz0 = 1; mz0 <= 8; mz0 += 4) {
        t.g[n].mx = 0.f; t.g[n].my = 0.f; t.g[n].mz0 = (float)mz0; t.g[n].pad = 0.f;
        t.g[n].w0 = (mz0 + 0 <= 8) ? 2.f : 0.f;
        t.g[n].w1 = (mz0 + 1 <= 8) ? 2.f : 0.f;
        t.g[n].w2 = (mz0 + 2 <= 8) ? 2.f : 0.f;
        t.g[n].w3 = (mz0 + 3 <= 8) ? 2.f : 0.f;
        n++;
    }
    for (int my = 1; my <= KMAXI; my++) {
        int L = ifsqrt(KMAXI * KMAXI - my * my);
        for (int mz0 = -L; mz0 <= L; mz0 += 4) {
            t.g[n].mx = 0.f; t.g[n].my = (float)my; t.g[n].mz0 = (float)mz0; t.g[n].pad = 0.f;
            t.g[n].w0 = (mz0 + 0 <= L) ? 2.f : 0.f;
            t.g[n].w1 = (mz0 + 1 <= L) ? 2.f : 0.f;
            t.g[n].w2 = (mz0 + 2 <= L) ? 2.f : 0.f;
            t.g[n].w3 = (mz0 + 3 <= L) ? 2.f : 0.f;
            n++;
        }
    }
    for (int mx = 1; mx <= KMAXI; mx++) {
        int L2 = ifsqrt(KMAXI * KMAXI - mx * mx);
        for (int my = -L2; my <= L2; my++) {
            int L = ifsqrt(KMAXI * KMAXI - mx * mx - my * my);
            for (int mz0 = -L; mz0 <= L; mz0 += 4) {
                t.g[n].mx = (float)mx; t.g[n].my = (float)my; t.g[n].mz0 = (float)mz0; t.g[n].pad = 0.f;
                t.g[n].w0 = (mz0 + 0 <= L) ? 2.f : 0.f;
                t.g[n].w1 = (mz0 + 1 <= L) ? 2.f : 0.f;
                t.g[n].w2 = (mz0 + 2 <= L) ? 2.f : 0.f;
                t.g[n].w3 = (mz0 + 3 <= L) ? 2.f : 0.f;
                n++;
            }
        }
    }
    // padding groups: weight 0, k2 > 0 for all 4 entries
    for (; n < NG_PAD; n++) {
        t.g[n].mx = 1.f; t.g[n].my = 0.f; t.g[n].mz0 = 0.f; t.g[n].pad = 0.f;
        t.g[n].w0 = 0.f; t.g[n].w1 = 0.f; t.g[n].w2 = 0.f; t.g[n].w3 = 0.f;
    }
    return t;
}
constexpr KGTable h_kg = make_kg();
__constant__ KGTable c_kg = h_kg;

#define WNORM_BLOCKS 32
#define RECIP_BASE   (REAL_BLOCKS + WNORM_BLOCKS)
#define RECIP_BLOCKS (NUM_BATCH * JG)
#define TOTAL_BLOCKS (RECIP_BASE + RECIP_BLOCKS)
#define PPB          (JG * 8)               // partials per batch (160)
#define NPART        (PPB * NUM_BATCH)

// scratch (no allocations). Partials/wnorm overwritten every call;
// g_ereal reset by its reader in k_final (zero invariant for replays).
__device__ float g_recip_part[NPART];
__device__ float g_wnorm[NUM_BATCH];
__device__ float g_ereal[N_ATOMS];

// ------------------------------------------------------------------
// fused main:
//   blocks [0, 512)        real space (coalesced pairs, warp segscan)
//   blocks [512, 544)      per-batch wnorm
//   blocks [544, 544+640)  recip: (batch b, group j). Stage 512 atoms as
//     (tx,ty,tz,q) + phasor (cos tz, sin tz) in SMEM once; loop 2 chunks.
//     Each warp: one k-GROUP per chunk -> 1 sincos + 3 rotations per atom.
// __launch_bounds__(256, 6): cap regs ~40 -> 6 blocks/SM (48 warps).
// ------------------------------------------------------------------
__global__ void __launch_bounds__(256, 6) k_main(
        const float* __restrict__ Qa,
        const float* __restrict__ rij,
        const int*   __restrict__ idx_i,
        const int*   __restrict__ idx_j,
        const float* __restrict__ R,
        const float* __restrict__ cell) {
    int bid = blockIdx.x;
    int tid = threadIdx.x;
    int warp = tid >> 5;
    int lane = tid & 31;

    if (bid < REAL_BLOCKS) {
        // ---------------- real space ----------------
        int gw = bid * 8 + warp;
        int base = gw * PAIRS_PER_WARP;
#pragma unroll
        for (int it = 0; it < PAIRS_PER_WARP / 32; it++) {
            int p = base + it * 32 + lane;          // coalesced
            int ii = idx_i[p];
            int jj = idx_j[p];
            float rr = rij[p];
            float fac = __ldg(&Qa[ii]) * __ldg(&Qa[jj]);

            // C-inf switch, fast path
            float x = (rr - 2.5f) * 0.2f;
            float f;
            if (x <= 0.0f)      f = 1.0f;
            else if (x >= 1.0f) f = 0.0f;
            else {
                float fp = __expf(-__frcp_rn(x));
                float fm = __expf(-__frcp_rn(1.0f - x));
                f = fm * __frcp_rn(fp + fm);
            }
            float damped = rsqrtf(fmaf(rr, rr, 1.0f));
            float coul = __frcp_rn(rr);

            // erfc via Abramowitz-Stegun 7.1.26 (abs err <= 1.5e-7)
            float xa = ALPHA_F * rr;
            float t = __frcp_rn(fmaf(0.3275911f, xa, 1.0f));
            float poly = t * fmaf(t, fmaf(t, fmaf(t, fmaf(t, 1.061405429f,
                                -1.453152027f), 1.421413741f),
                                -0.284496736f), 0.254829592f);
            float er = poly * __expf(-xa * xa);

            float pw = fac * (f * damped + (1.0f - f) * coul) * er;

            // warp segmented reduction over sorted ii
            int prev = __shfl_up_sync(FULL, ii, 1);
            bool head = (lane == 0) || (ii != prev);
            unsigned hm = __ballot_sync(FULL, head);
            unsigned below = hm & (0xFFFFFFFFu >> (31 - lane));
            int hp = 31 - __clz(below);
            float s = pw;
#pragma unroll
            for (int d = 1; d < 32; d <<= 1) {
                float v = __shfl_up_sync(FULL, s, d);
                if (lane >= hp + d) s += v;
            }
            bool lastv = (lane == 31) || ((hm >> (lane + 1)) & 1u);
            if (lastv) atomicAdd(&g_ereal[ii], s);
        }
    } else if (bid < RECIP_BASE) {
        // ---------------- per-batch wnorm (overwrite) ----------------
        int b = bid - REAL_BLOCKS;
        __shared__ float sw[8];
        float acc = 0.0f;
        for (int a = tid; a < ATOMS_PER_BATCH; a += 256) {
            float q = Qa[b * ATOMS_PER_BATCH + a];
            acc = fmaf(q, q, acc + EPS_F);
        }
#pragma unroll
        for (int o = 16; o > 0; o >>= 1) acc += __shfl_down_sync(FULL, acc, o);
        if (lane == 0) sw[warp] = acc;
        __syncthreads();
        if (tid == 0) {
            float tot = 0.0f;
#pragma unroll
            for (int w2 = 0; w2 < 8; w2++) tot += sw[w2];
            g_wnorm[b] = tot;
        }
    } else {
        // ---------------- reciprocal space (column recursion) ----------------
        int idx = bid - RECIP_BASE;
        int b = idx & (NUM_BATCH - 1);          // batch
        int j = idx >> 5;                       // chunk group 0..JG-1

        __shared__ float4 sA[ATOMS_PER_BATCH];  // (tx, ty, tz, q)
        __shared__ float2 sE[ATOMS_PER_BATCH];  // (cos tz, sin tz)

        float ax = TWO_PI_F * __frcp_rn(cell[b * 9 + 0]);
        float ay = TWO_PI_F * __frcp_rn(cell[b * 9 + 4]);
        float az = TWO_PI_F * __frcp_rn(cell[b * 9 + 8]);

        for (int a = tid; a < ATOMS_PER_BATCH; a += 256) {
            int n = b * ATOMS_PER_BATCH + a;
            float4 v;
            v.x = R[n * 3 + 0] * ax;
            v.y = R[n * 3 + 1] * ay;
            v.z = R[n * 3 + 2] * az;
            v.w = Qa[n];
            sA[a] = v;
            float cz, sz;
            __sincosf(v.z, &sz, &cz);
            sE[a] = make_float2(cz, sz);
        }
        __syncthreads();

        float blockAcc = 0.0f;                  // lane0 accumulator across chunks

#pragma unroll
        for (int c = 0; c < CHUNKS_PER_BLOCK; c++) {
            int grp = (j + c * JG) * 8 + warp;  // one group per warp per chunk
            const KGroup& G = c_kg.g[grp];
            float mx = G.mx, my = G.my, mz0 = G.mz0;

            float cr0 = 0.f, ci0 = 0.f, cr1 = 0.f, ci1 = 0.f;
            float cr2 = 0.f, ci2 = 0.f, cr3 = 0.f, ci3 = 0.f;

#pragma unroll 4
            for (int a = lane; a < ATOMS_PER_BATCH; a += 32) {
                float4 v = sA[a];
                float2 ez = sE[a];
                float q = v.w;
                float dxy = fmaf(mx, v.x, my * v.y);
                float d0 = fmaf(mz0, v.z, dxy);
                float s0, c0;
                __sincosf(d0, &s0, &c0);
                cr0 = fmaf(q, c0, cr0); ci0 = fmaf(q, s0, ci0);
                float c1 = fmaf(c0, ez.x, -s0 * ez.y);
                float s1 = fmaf(s0, ez.x,  c0 * ez.y);
                cr1 = fmaf(q, c1, cr1); ci1 = fmaf(q, s1, ci1);
                float c2 = fmaf(c1, ez.x, -s1 * ez.y);
                float s2 = fmaf(s1, ez.x,  c1 * ez.y);
                cr2 = fmaf(q, c2, cr2); ci2 = fmaf(q, s2, ci2);
                float c3 = fmaf(c2, ez.x, -s2 * ez.y);
                float s3 = fmaf(s2, ez.x,  c2 * ez.y);
                cr3 = fmaf(q, c3, cr3); ci3 = fmaf(q, s3, ci3);
            }
#pragma unroll
            for (int o = 16; o > 0; o >>= 1) {
                cr0 += __shfl_down_sync(FULL, cr0, o);
                ci0 += __shfl_down_sync(FULL, ci0, o);
                cr1 += __shfl_down_sync(FULL, cr1, o);
                ci1 += __shfl_down_sync(FULL, ci1, o);
                cr2 += __shfl_down_sync(FULL, cr2, o);
                ci2 += __shfl_down_sync(FULL, ci2, o);
                cr3 += __shfl_down_sync(FULL, cr3, o);
                ci3 += __shfl_down_sync(FULL, ci3, o);
            }
            if (lane == 0) {
                float kx = mx * ax, ky = my * ay;
                float kxy2 = kx * kx + ky * ky;
                float kz, k2, qg;
                kz = mz0 * az;                 k2 = kxy2 + kz * kz;
                qg = __expf(-K2FAC_F * k2) * __frcp_rn(k2);
                blockAcc = fmaf(G.w0 * qg, fmaf(cr0, cr0, ci0 * ci0), blockAcc);
                kz = (mz0 + 1.f) * az;         k2 = kxy2 + kz * kz;
                qg = __expf(-K2FAC_F * k2) * __frcp_rn(k2);
                blockAcc = fmaf(G.w1 * qg, fmaf(cr1, cr1, ci1 * ci1), blockAcc);
                kz = (mz0 + 2.f) * az;         k2 = kxy2 + kz * kz;
                qg = __expf(-K2FAC_F * k2) * __frcp_rn(k2);
                blockAcc = fmaf(G.w2 * qg, fmaf(cr2, cr2, ci2 * ci2), blockAcc);
                kz = (mz0 + 3.f) * az;         k2 = kxy2 + kz * kz;
                qg = __expf(-K2FAC_F * k2) * __frcp_rn(k2);
                blockAcc = fmaf(G.w3 * qg, fmaf(cr3, cr3, ci3 * ci3), blockAcc);
            }
        }
        if (lane == 0)
            g_recip_part[(j * 8 + warp) * NUM_BATCH + b] = blockAcc;   // plain store
    }
}

// ------------------------------------------------------------------
// finalize: launched with PDL (programmatic stream serialization) so
// its launch/ramp overlaps k_main's tail; cudaGridDependencySynchronize
// orders it after all k_main memory. 128 blocks x 128 threads.
// g_ereal reset by its reader (zero invariant for replays).
// ------------------------------------------------------------------
__global__ void k_final(const float* __restrict__ Qa,
                        const float* __restrict__ cell,
                        float* __restrict__ out) {
#if __CUDA_ARCH__ >= 900
    cudaGridDependencySynchronize();
#endif
    int n = blockIdx.x * 128 + threadIdx.x;
    int b = n >> 9;                 // same for whole block (128 | 512)
    int a = threadIdx.x;
    __shared__ float srec;

    float er = g_ereal[n];
    g_ereal[n] = 0.0f;              // restore invariant for next replay

    if (a < 32) {
        float t = 0.0f;
        for (int p = a; p < PPB; p += 32)
            t += g_recip_part[p * NUM_BATCH + b];
#pragma unroll
        for (int o = 16; o > 0; o >>= 1) t += __shfl_down_sync(FULL, t, o);
        if (a == 0) srec = t;
    }
    __syncthreads();
    float rec = srec;

    float q = Qa[n];
    float q2 = q * q;
    float w = q2 + EPS_F;
    float wnorm = g_wnorm[b];

    float Lx = cell[b * 9 + 0];
    float Ly = cell[b * 9 + 4];
    float Lz = cell[b * 9 + 8];
    float erec = (w / wnorm) * (TWO_PI_F / (Lx * Ly * Lz)) * rec;
    out[n] = er + erec - SELF_F * q2;
}

// ------------------------------------------------------------------
extern "C" void kernel_launch(void* const* d_in, const int* in_sizes, int n_in,
                              void* d_out, int out_size) {
    const float* Qa    = (const float*)d_in[0];
    const float* rij   = (const float*)d_in[1];
    const float* R     = (const float*)d_in[2];
    const float* cell  = (const float*)d_in[3];
    const int*   idx_i = (const int*)d_in[5];
    const int*   idx_j = (const int*)d_in[6];
    float* out = (float*)d_out;

    k_main<<<TOTAL_BLOCKS, 256>>>(Qa, rij, idx_i, idx_j, R, cell);

    // k_final with programmatic dependent launch: overlap its launch/ramp
    // with k_main's tail; the in-kernel grid sync enforces ordering.
    cudaLaunchConfig_t cfg = {};
    cfg.gridDim  = dim3(N_ATOMS / 128);
    cfg.blockDim = dim3(128);
    cfg.dynamicSmemBytes = 0;
    cfg.stream = 0;
    cudaLaunchAttribute attrs[1];
    attrs[0].id = cudaLaunchAttributeProgrammaticStreamSerialization;
    attrs[0].val.programmaticStreamSerializationAllowed = 1;
    cfg.attrs = attrs;
    cfg.numAttrs = 1;
    cudaError_t e = cudaLaunchKernelEx(&cfg, k_final, Qa, cell, out);
    if (e != cudaSuccess) {
        // fallback: plain launch (ordering via stream)
        k_final<<<N_ATOMS / 128, 128>>>(Qa, cell, out);
    }
}

// round 17
// speedup vs baseline: 1.0695x; 1.0695x over previous
#include <cuda_runtime.h>
#include <cuda_bf16.h>
#include <math.h>

// ---- static problem config (matches reference) ----
#define N_ATOMS 16384
#define NUM_BATCH 32
#define ATOMS_PER_BATCH 512
#define N_PAIRS 1048576

#define ALPHA_F       0.401f            // 4/10 + 0.001
#define K2FAC_F       1.5547167f        // 0.25 / ALPHA^2
#define TWO_PI_F      6.283185307179586f
#define SELF_F        0.2262400229976503f   // ALPHA / sqrt(pi)
#define EPS_F         1e-8f
#define FULL 0xFFFFFFFFu

#define REAL_BLOCKS 256                 // 256 blocks * 8 warps * 512 pairs = 1M
#define PAIRS_PER_WARP 512
#define KMAXI 8

// ------------------------------------------------------------------
// Compile-time k-table organized as GROUPS of 4 consecutive mz within
// one (mx,my) column of the canonical half lattice. A warp computes one
// sincos for the first entry of a group and derives the other three by
// complex rotation with the per-atom phasor e^{i*theta_z}.
// canonical: mx>0 | (mx=0 & my>0) | (mx=0 & my=0 & mz>0); 0<|k|^2<=64.
// ------------------------------------------------------------------
struct KGroup { float mx, my, mz0, pad, w0, w1, w2, w3; };

constexpr int ifsqrt(int v) { int r = 0; while ((r + 1) * (r + 1) <= v) r++; return r; }

constexpr int count_groups() {
    int n = 0;
    n += 2;                                        // (0,0): mz 1..8 -> 2 groups
    for (int my = 1; my <= KMAXI; my++) {          // mx=0 columns
        int L = ifsqrt(KMAXI * KMAXI - my * my);
        n += (2 * L + 1 + 3) / 4;
    }
    for (int mx = 1; mx <= KMAXI; mx++) {
        int L2 = ifsqrt(KMAXI * KMAXI - mx * mx);
        for (int my = -L2; my <= L2; my++) {
            int L = ifsqrt(KMAXI * KMAXI - mx * mx - my * my);
            n += (2 * L + 1 + 3) / 4;
        }
    }
    return n;
}
constexpr int NG     = count_groups();
constexpr int NG_PAD = ((NG + 79) / 80) * 80;      // multiple of 80 -> KBg mult of 10
constexpr int KBg    = NG_PAD / 8;                 // chunks of 8 groups
constexpr int JG     = 10;                         // chunk groups per batch
static_assert(KBg % JG == 0, "balanced chunks");
constexpr int CHUNKS_PER_BLOCK = KBg / JG;         // 4

struct KGTable { KGroup g[NG_PAD]; };

constexpr KGTable make_kg() {
    KGTable t{};
    int n = 0;
    // (0,0): mz 1..8
    for (int mz0 = 1; mz0 <= 8; mz0 += 4) {
        t.g[n].mx = 0.f; t.g[n].my = 0.f; t.g[n].mz0 = (float)mz0; t.g[n].pad = 0.f;
        t.g[n].w0 = (mz0 + 0 <= 8) ? 2.f : 0.f;
        t.g[n].w1 = (mz0 + 1 <= 8) ? 2.f : 0.f;
        t.g[n].w2 = (mz0 + 2 <= 8) ? 2.f : 0.f;
        t.g[n].w3 = (mz0 + 3 <= 8) ? 2.f : 0.f;
        n++;
    }
    for (int my = 1; my <= KMAXI; my++) {
        int L = ifsqrt(KMAXI * KMAXI - my * my);
        for (int mz0 = -L; mz0 <= L; mz0 += 4) {
            t.g[n].mx = 0.f; t.g[n].my = (float)my; t.g[n].mz0 = (float)mz0; t.g[n].pad = 0.f;
            t.g[n].w0 = (mz0 + 0 <= L) ? 2.f : 0.f;
            t.g[n].w1 = (mz0 + 1 <= L) ? 2.f : 0.f;
            t.g[n].w2 = (mz0 + 2 <= L) ? 2.f : 0.f;
            t.g[n].w3 = (mz0 + 3 <= L) ? 2.f : 0.f;
            n++;
        }
    }
    for (int mx = 1; mx <= KMAXI; mx++) {
        int L2 = ifsqrt(KMAXI * KMAXI - mx * mx);
        for (int my = -L2; my <= L2; my++) {
            int L = ifsqrt(KMAXI * KMAXI - mx * mx - my * my);
            for (int mz0 = -L; mz0 <= L; mz0 += 4) {
                t.g[n].mx = (float)mx; t.g[n].my = (float)my; t.g[n].mz0 = (float)mz0; t.g[n].pad = 0.f;
                t.g[n].w0 = (mz0 + 0 <= L) ? 2.f : 0.f;
                t.g[n].w1 = (mz0 + 1 <= L) ? 2.f : 0.f;
                t.g[n].w2 = (mz0 + 2 <= L) ? 2.f : 0.f;
                t.g[n].w3 = (mz0 + 3 <= L) ? 2.f : 0.f;
                n++;
            }
        }
    }
    // padding groups: weight 0, k2 > 0 for all 4 entries
    for (; n < NG_PAD; n++) {
        t.g[n].mx = 1.f; t.g[n].my = 0.f; t.g[n].mz0 = 0.f; t.g[n].pad = 0.f;
        t.g[n].w0 = 0.f; t.g[n].w1 = 0.f; t.g[n].w2 = 0.f; t.g[n].w3 = 0.f;
    }
    return t;
}
constexpr KGTable h_kg = make_kg();
__constant__ KGTable c_kg = h_kg;

#define WNORM_BLOCKS 32
#define RECIP_BASE   (REAL_BLOCKS + WNORM_BLOCKS)
#define RECIP_BLOCKS (NUM_BATCH * JG)
#define TOTAL_BLOCKS (RECIP_BASE + RECIP_BLOCKS)   // 256+32+320 = 608 (single wave)
#define PPB          (JG * 8)               // partials per batch (80)
#define NPART        (PPB * NUM_BATCH)

// scratch (no allocations). Partials/wnorm overwritten every call;
// g_ereal reset by its reader in k_final (zero invariant for replays).
__device__ float g_recip_part[NPART];
__device__ float g_wnorm[NUM_BATCH];
__device__ float g_ereal[N_ATOMS];

// ------------------------------------------------------------------
// fused main (608 blocks = ONE resident wave at ~5 blocks/SM):
//   blocks [0, 256)        real space (coalesced pairs, warp segscan)
//   blocks [256, 288)      per-batch wnorm
//   blocks [288, 608)      recip: (batch b, group j). Stage 512 atoms as
//     (tx,ty,tz,q) + phasor (cos tz, sin tz) in SMEM once; loop 4 chunks.
//     Each warp: one k-GROUP per chunk -> 1 sincos + 3 rotations per atom.
// ------------------------------------------------------------------
__global__ void __launch_bounds__(256) k_main(
        const float* __restrict__ Qa,
        const float* __restrict__ rij,
        const int*   __restrict__ idx_i,
        const int*   __restrict__ idx_j,
        const float* __restrict__ R,
        const float* __restrict__ cell) {
    int bid = blockIdx.x;
    int tid = threadIdx.x;
    int warp = tid >> 5;
    int lane = tid & 31;

    if (bid < REAL_BLOCKS) {
        // ---------------- real space ----------------
        int gw = bid * 8 + warp;
        int base = gw * PAIRS_PER_WARP;
#pragma unroll 2
        for (int it = 0; it < PAIRS_PER_WARP / 32; it++) {
            int p = base + it * 32 + lane;          // coalesced
            int ii = idx_i[p];
            int jj = idx_j[p];
            float rr = rij[p];
            float fac = __ldg(&Qa[ii]) * __ldg(&Qa[jj]);

            // C-inf switch, fast path
            float x = (rr - 2.5f) * 0.2f;
            float f;
            if (x <= 0.0f)      f = 1.0f;
            else if (x >= 1.0f) f = 0.0f;
            else {
                float fp = __expf(-__frcp_rn(x));
                float fm = __expf(-__frcp_rn(1.0f - x));
                f = fm * __frcp_rn(fp + fm);
            }
            float damped = rsqrtf(fmaf(rr, rr, 1.0f));
            float coul = __frcp_rn(rr);

            // erfc via Abramowitz-Stegun 7.1.26 (abs err <= 1.5e-7)
            float xa = ALPHA_F * rr;
            float t = __frcp_rn(fmaf(0.3275911f, xa, 1.0f));
            float poly = t * fmaf(t, fmaf(t, fmaf(t, fmaf(t, 1.061405429f,
                                -1.453152027f), 1.421413741f),
                                -0.284496736f), 0.254829592f);
            float er = poly * __expf(-xa * xa);

            float pw = fac * (f * damped + (1.0f - f) * coul) * er;

            // warp segmented reduction over sorted ii
            int prev = __shfl_up_sync(FULL, ii, 1);
            bool head = (lane == 0) || (ii != prev);
            unsigned hm = __ballot_sync(FULL, head);
            unsigned below = hm & (0xFFFFFFFFu >> (31 - lane));
            int hp = 31 - __clz(below);
            float s = pw;
#pragma unroll
            for (int d = 1; d < 32; d <<= 1) {
                float v = __shfl_up_sync(FULL, s, d);
                if (lane >= hp + d) s += v;
            }
            bool lastv = (lane == 31) || ((hm >> (lane + 1)) & 1u);
            if (lastv) atomicAdd(&g_ereal[ii], s);
        }
    } else if (bid < RECIP_BASE) {
        // ---------------- per-batch wnorm (overwrite) ----------------
        int b = bid - REAL_BLOCKS;
        __shared__ float sw[8];
        float acc = 0.0f;
        for (int a = tid; a < ATOMS_PER_BATCH; a += 256) {
            float q = Qa[b * ATOMS_PER_BATCH + a];
            acc = fmaf(q, q, acc + EPS_F);
        }
#pragma unroll
        for (int o = 16; o > 0; o >>= 1) acc += __shfl_down_sync(FULL, acc, o);
        if (lane == 0) sw[warp] = acc;
        __syncthreads();
        if (tid == 0) {
            float tot = 0.0f;
#pragma unroll
            for (int w2 = 0; w2 < 8; w2++) tot += sw[w2];
            g_wnorm[b] = tot;
        }
    } else {
        // ---------------- reciprocal space (column recursion) ----------------
        int idx = bid - RECIP_BASE;
        int b = idx & (NUM_BATCH - 1);          // batch
        int j = idx >> 5;                       // chunk group 0..JG-1

        __shared__ float4 sA[ATOMS_PER_BATCH];  // (tx, ty, tz, q)
        __shared__ float2 sE[ATOMS_PER_BATCH];  // (cos tz, sin tz)

        float ax = TWO_PI_F * __frcp_rn(cell[b * 9 + 0]);
        float ay = TWO_PI_F * __frcp_rn(cell[b * 9 + 4]);
        float az = TWO_PI_F * __frcp_rn(cell[b * 9 + 8]);

        for (int a = tid; a < ATOMS_PER_BATCH; a += 256) {
            int n = b * ATOMS_PER_BATCH + a;
            float4 v;
            v.x = R[n * 3 + 0] * ax;
            v.y = R[n * 3 + 1] * ay;
            v.z = R[n * 3 + 2] * az;
            v.w = Qa[n];
            sA[a] = v;
            float cz, sz;
            __sincosf(v.z, &sz, &cz);
            sE[a] = make_float2(cz, sz);
        }
        __syncthreads();

        float blockAcc = 0.0f;                  // lane0 accumulator across chunks

#pragma unroll
        for (int c = 0; c < CHUNKS_PER_BLOCK; c++) {
            int grp = (j + c * JG) * 8 + warp;  // one group per warp per chunk
            const KGroup& G = c_kg.g[grp];
            float mx = G.mx, my = G.my, mz0 = G.mz0;

            float cr0 = 0.f, ci0 = 0.f, cr1 = 0.f, ci1 = 0.f;
            float cr2 = 0.f, ci2 = 0.f, cr3 = 0.f, ci3 = 0.f;

#pragma unroll 4
            for (int a = lane; a < ATOMS_PER_BATCH; a += 32) {
                float4 v = sA[a];
                float2 ez = sE[a];
                float q = v.w;
                float dxy = fmaf(mx, v.x, my * v.y);
                float d0 = fmaf(mz0, v.z, dxy);
                float s0, c0;
                __sincosf(d0, &s0, &c0);
                cr0 = fmaf(q, c0, cr0); ci0 = fmaf(q, s0, ci0);
                float c1 = fmaf(c0, ez.x, -s0 * ez.y);
                float s1 = fmaf(s0, ez.x,  c0 * ez.y);
                cr1 = fmaf(q, c1, cr1); ci1 = fmaf(q, s1, ci1);
                float c2 = fmaf(c1, ez.x, -s1 * ez.y);
                float s2 = fmaf(s1, ez.x,  c1 * ez.y);
                cr2 = fmaf(q, c2, cr2); ci2 = fmaf(q, s2, ci2);
                float c3 = fmaf(c2, ez.x, -s2 * ez.y);
                float s3 = fmaf(s2, ez.x,  c2 * ez.y);
                cr3 = fmaf(q, c3, cr3); ci3 = fmaf(q, s3, ci3);
            }
#pragma unroll
            for (int o = 16; o > 0; o >>= 1) {
                cr0 += __shfl_down_sync(FULL, cr0, o);
                ci0 += __shfl_down_sync(FULL, ci0, o);
                cr1 += __shfl_down_sync(FULL, cr1, o);
                ci1 += __shfl_down_sync(FULL, ci1, o);
                cr2 += __shfl_down_sync(FULL, cr2, o);
                ci2 += __shfl_down_sync(FULL, ci2, o);
                cr3 += __shfl_down_sync(FULL, cr3, o);
                ci3 += __shfl_down_sync(FULL, ci3, o);
            }
            if (lane == 0) {
                float kx = mx * ax, ky = my * ay;
                float kxy2 = kx * kx + ky * ky;
                float kz, k2, qg;
                kz = mz0 * az;                 k2 = kxy2 + kz * kz;
                qg = __expf(-K2FAC_F * k2) * __frcp_rn(k2);
                blockAcc = fmaf(G.w0 * qg, fmaf(cr0, cr0, ci0 * ci0), blockAcc);
                kz = (mz0 + 1.f) * az;         k2 = kxy2 + kz * kz;
                qg = __expf(-K2FAC_F * k2) * __frcp_rn(k2);
                blockAcc = fmaf(G.w1 * qg, fmaf(cr1, cr1, ci1 * ci1), blockAcc);
                kz = (mz0 + 2.f) * az;         k2 = kxy2 + kz * kz;
                qg = __expf(-K2FAC_F * k2) * __frcp_rn(k2);
                blockAcc = fmaf(G.w2 * qg, fmaf(cr2, cr2, ci2 * ci2), blockAcc);
                kz = (mz0 + 3.f) * az;         k2 = kxy2 + kz * kz;
                qg = __expf(-K2FAC_F * k2) * __frcp_rn(k2);
                blockAcc = fmaf(G.w3 * qg, fmaf(cr3, cr3, ci3 * ci3), blockAcc);
            }
        }
        if (lane == 0)
            g_recip_part[(j * 8 + warp) * NUM_BATCH + b] = blockAcc;   // plain store
    }
}

// ------------------------------------------------------------------
// finalize: launched with PDL (programmatic stream serialization) so
// its launch/ramp overlaps k_main's tail; cudaGridDependencySynchronize
// orders it after all k_main memory. 128 blocks x 128 threads.
// g_ereal reset by its reader (zero invariant for replays).
// ------------------------------------------------------------------
__global__ void k_final(const float* __restrict__ Qa,
                        const float* __restrict__ cell,
                        float* __restrict__ out) {
#if __CUDA_ARCH__ >= 900
    cudaGridDependencySynchronize();
#endif
    int n = blockIdx.x * 128 + threadIdx.x;
    int b = n >> 9;                 // same for whole block (128 | 512)
    int a = threadIdx.x;
    __shared__ float srec;

    float er = g_ereal[n];
    g_ereal[n] = 0.0f;              // restore invariant for next replay

    if (a < 32) {
        float t = 0.0f;
        for (int p = a; p < PPB; p += 32)
            t += g_recip_part[p * NUM_BATCH + b];
#pragma unroll
        for (int o = 16; o > 0; o >>= 1) t += __shfl_down_sync(FULL, t, o);
        if (a == 0) srec = t;
    }
    __syncthreads();
    float rec = srec;

    float q = Qa[n];
    float q2 = q * q;
    float w = q2 + EPS_F;
    float wnorm = g_wnorm[b];

    float Lx = cell[b * 9 + 0];
    float Ly = cell[b * 9 + 4];
    float Lz = cell[b * 9 + 8];
    float erec = (w / wnorm) * (TWO_PI_F / (Lx * Ly * Lz)) * rec;
    out[n] = er + erec - SELF_F * q2;
}

// ------------------------------------------------------------------
extern "C" void kernel_launch(void* const* d_in, const int* in_sizes, int n_in,
                              void* d_out, int out_size) {
    const float* Qa    = (const float*)d_in[0];
    const float* rij   = (const float*)d_in[1];
    const float* R     = (const float*)d_in[2];
    const float* cell  = (const float*)d_in[3];
    const int*   idx_i = (const int*)d_in[5];
    const int*   idx_j = (const int*)d_in[6];
    float* out = (float*)d_out;

    k_main<<<TOTAL_BLOCKS, 256>>>(Qa, rij, idx_i, idx_j, R, cell);

    // k_final with programmatic dependent launch: overlap its launch/ramp
    // with k_main's tail; the in-kernel grid sync enforces ordering.
    cudaLaunchConfig_t cfg = {};
    cfg.gridDim  = dim3(N_ATOMS / 128);
    cfg.blockDim = dim3(128);
    cfg.dynamicSmemBytes = 0;
    cfg.stream = 0;
    cudaLaunchAttribute attrs[1];
    attrs[0].id = cudaLaunchAttributeProgrammaticStreamSerialization;
    attrs[0].val.programmaticStreamSerializationAllowed = 1;
    cfg.attrs = attrs;
    cfg.numAttrs = 1;
    cudaError_t e = cudaLaunchKernelEx(&cfg, k_final, Qa, cell, out);
    if (e != cudaSuccess) {
        // fallback: plain launch (ordering via stream)
        k_final<<<N_ATOMS / 128, 128>>>(Qa, cell, out);
    }
}